// round 4
// baseline (speedup 1.0000x reference)
#include <cuda_runtime.h>

#define BB 2048
#define SS 1024
#define FF 64
#define BI 64
#define BJ 64
#define KC 32
#define TI 4
#define TJ 4

typedef unsigned long long u64;

#define MUL2(d,a,b)   asm("mul.rn.f32x2 %0, %1, %2;" : "=l"(d) : "l"(a), "l"(b))
#define FMA2(d,a,b,c) asm("fma.rn.f32x2 %0, %1, %2, %3;" : "=l"(d) : "l"(a), "l"(b), "l"(c))
#define PACK2(d,x)    asm("mov.b64 %0, {%1, %1};" : "=l"(d) : "r"(x))

// Precomputed half-angle sin/cos tables, f-major: [f][row]
__device__ float g_cX[FF * BB];
__device__ float g_sX[FF * BB];
__device__ float g_cS[FF * SS];
__device__ float g_sS[FF * SS];

// Coalesced load -> smem transpose -> coalesced f-major store. 32 rows/block.
// Also folds the out[i]=b init (blocks 0..7).
__global__ __launch_bounds__(256) void precomp_kernel(const float* __restrict__ X,
                                                      const float* __restrict__ Sp,
                                                      const float* __restrict__ b,
                                                      float* __restrict__ out) {
    __shared__ float sc[FF][33];
    __shared__ float ss[FF][33];
    const int blk = blockIdx.x;       // 0..95: [0,64) -> X, [64,96) -> S
    const int tid = threadIdx.x;

    const float* src;
    float *dstC, *dstS;
    int N, i0;
    if (blk < 64) { src = X;  dstC = g_cX; dstS = g_sX; N = BB; i0 = blk * 32; }
    else          { src = Sp; dstC = g_cS; dstS = g_sS; N = SS; i0 = (blk - 64) * 32; }

    // 32 rows x 64 f = 2048 elems, 8 passes. Lanes step f -> coalesced gmem reads.
#pragma unroll
    for (int p = 0; p < 8; p++) {
        int l = p * 256 + tid;
        int r = l >> 6;          // 0..31
        int f = l & 63;
        float v = src[(i0 + r) * FF + f];
        float s, c;
        __sincosf(0.5f * v, &s, &c);
        sc[f][r] = c;            // stride-33 rows: conflict-free
        ss[f][r] = s;
    }
    __syncthreads();
    // Write out f-major: lanes step i -> coalesced gmem writes.
#pragma unroll
    for (int p = 0; p < 8; p++) {
        int l = p * 256 + tid;
        int f = l >> 5;          // 0..63
        int i = l & 31;
        dstC[f * N + i0 + i] = sc[f][i];
        dstS[f * N + i0 + i] = ss[f][i];
    }
    if (blk < 8) out[blk * 256 + tid] = b[0];
}

__global__ __launch_bounds__(256, 2) void main_kernel(const float* __restrict__ W,
                                                      float* __restrict__ out) {
    __shared__ __align__(16) float sCX[KC][BI];
    __shared__ __align__(16) float sSX[KC][BI];
    __shared__ __align__(16) float sCS[KC][BJ];
    __shared__ __align__(16) float sSS[KC][BJ];
    __shared__ float sW[BJ];

    const int tid = threadIdx.x;
    const int tx = tid & 15;   // j-direction (16 threads * TJ=4 -> 64 j)
    const int ty = tid >> 4;   // i-direction (16 threads * TI=4 -> 64 i)
    const int i0 = blockIdx.x * BI;
    const int j0 = blockIdx.y * BJ;

    if (tid < BJ) sW[tid] = W[j0 + tid];

    // acc pairs along j: acc[a][bp] = {K_j0, K_j1} running products, init {1,1}
    u64 acc[TI][TJ / 2];
#pragma unroll
    for (int a = 0; a < TI; a++)
#pragma unroll
        for (int bp = 0; bp < TJ / 2; bp++) acc[a][bp] = 0x3F8000003F800000ULL;

    for (int fc = 0; fc < FF; fc += KC) {
        __syncthreads();  // protect previous chunk (and sW on first pass)
        // Vectorized fill: per array 2048 floats = 512 float4 -> 2 rounds.
#pragma unroll
        for (int r = 0; r < 2; r++) {
            int l = r * 256 + tid;
            int f = l >> 4;
            int q = (l & 15) * 4;
            *(float4*)&sCX[f][q] = *(const float4*)&g_cX[(fc + f) * BB + i0 + q];
            *(float4*)&sSX[f][q] = *(const float4*)&g_sX[(fc + f) * BB + i0 + q];
            *(float4*)&sCS[f][q] = *(const float4*)&g_cS[(fc + f) * SS + j0 + q];
            *(float4*)&sSS[f][q] = *(const float4*)&g_sS[(fc + f) * SS + j0 + q];
        }
        __syncthreads();

#pragma unroll 4
        for (int f = 0; f < KC; f++) {
            float4 cx4 = *(const float4*)&sCX[f][ty * TI];
            float4 sx4 = *(const float4*)&sSX[f][ty * TI];
            float4 cj4 = *(const float4*)&sCS[f][tx * TJ];
            float4 sj4 = *(const float4*)&sSS[f][tx * TJ];

            // j-pairs: free register-pair reinterpret of the float4s
            union { float4 v; u64 p[2]; } ucj, usj;
            ucj.v = cj4; usj.v = sj4;

            // i-broadcast packs: mov.b64 {r,r} -> ALU pipe (idle)
            u64 cxp[TI], sxp[TI];
            PACK2(cxp[0], __float_as_uint(cx4.x)); PACK2(sxp[0], __float_as_uint(sx4.x));
            PACK2(cxp[1], __float_as_uint(cx4.y)); PACK2(sxp[1], __float_as_uint(sx4.y));
            PACK2(cxp[2], __float_as_uint(cx4.z)); PACK2(sxp[2], __float_as_uint(sx4.z));
            PACK2(cxp[3], __float_as_uint(cx4.w)); PACK2(sxp[3], __float_as_uint(sx4.w));

#pragma unroll
            for (int a = 0; a < TI; a++) {
#pragma unroll
                for (int bp = 0; bp < TJ / 2; bp++) {
                    u64 t;
                    MUL2(t, sxp[a], usj.p[bp]);          // sx*sj (x2)
                    FMA2(t, cxp[a], ucj.p[bp], t);       // t = cos((x-s)/2) (x2)
                    MUL2(acc[a][bp], acc[a][bp], t);     // running product (x2)
                }
            }
        }
    }

    // K = (prod t)^2, weight by W, reduce over the 16 tx threads.
#pragma unroll
    for (int a = 0; a < TI; a++) {
        float p = 0.0f;
#pragma unroll
        for (int bp = 0; bp < TJ / 2; bp++) {
            float t0 = __uint_as_float((unsigned)(acc[a][bp] & 0xffffffffu));
            float t1 = __uint_as_float((unsigned)(acc[a][bp] >> 32));
            p = fmaf(t0 * t0, sW[tx * TJ + bp * 2 + 0], p);
            p = fmaf(t1 * t1, sW[tx * TJ + bp * 2 + 1], p);
        }
#pragma unroll
        for (int off = 8; off > 0; off >>= 1)
            p += __shfl_down_sync(0xffffffffu, p, off, 16);
        if (tx == 0) atomicAdd(&out[i0 + ty * TI + a], p);
    }
}

extern "C" void kernel_launch(void* const* d_in, const int* in_sizes, int n_in,
                              void* d_out, int out_size) {
    const float* X  = (const float*)d_in[0];  // [2048, 64]
    const float* Sp = (const float*)d_in[1];  // [1024, 64]
    const float* W  = (const float*)d_in[2];  // [1, 1024]
    const float* b  = (const float*)d_in[3];  // [1]
    float* out = (float*)d_out;               // [2048]

    precomp_kernel<<<96, 256>>>(X, Sp, b, out);   // tables + out=b init

    dim3 grid(BB / BI, SS / BJ);  // 32 x 16 = 512 CTAs
    main_kernel<<<grid, 256>>>(W, out);
}

// round 5
// speedup vs baseline: 1.8780x; 1.8780x over previous
#include <cuda_runtime.h>
#include <cuda_fp16.h>

#define BB 2048
#define SS 1024
#define FF 64
#define FP (FF / 2)      // 32 feature-pairs
#define BI 64
#define BJ 64
#define TI 4
#define TJ 4

// Precomputed half-angle sin/cos tables in fp16, f-pair-major:
// g_cX2[fp*BB + i] = {cos(X[i][2fp]/2), cos(X[i][2fp+1]/2)}
__device__ __half2 g_cX2[FP * BB];
__device__ __half2 g_sX2[FP * BB];
__device__ __half2 g_cS2[FP * SS];
__device__ __half2 g_sS2[FP * SS];

// Coalesced load -> fp32 sincos -> smem transpose -> packed half2 f-pair-major
// stores. 32 rows per block. Blocks 0..7 also init out[i] = b.
__global__ __launch_bounds__(256) void precomp_kernel(const float* __restrict__ X,
                                                      const float* __restrict__ Sp,
                                                      const float* __restrict__ b,
                                                      float* __restrict__ out) {
    __shared__ float sc[FF][33];
    __shared__ float ss[FF][33];
    const int blk = blockIdx.x;       // 0..95: [0,64) -> X, [64,96) -> S
    const int tid = threadIdx.x;

    const float* src;
    __half2 *dstC, *dstS;
    int N, i0;
    if (blk < 64) { src = X;  dstC = g_cX2; dstS = g_sX2; N = BB; i0 = blk * 32; }
    else          { src = Sp; dstC = g_cS2; dstS = g_sS2; N = SS; i0 = (blk - 64) * 32; }

    // Read 32 rows x 64 f = 2048 elems (8 passes, lanes step f -> coalesced).
#pragma unroll
    for (int p = 0; p < 8; p++) {
        int l = p * 256 + tid;
        int r = l >> 6;          // 0..31
        int f = l & 63;
        float v = src[(i0 + r) * FF + f];
        float s, c;
        __sincosf(0.5f * v, &s, &c);
        sc[f][r] = c;            // stride-33 rows: conflict-free
        ss[f][r] = s;
    }
    __syncthreads();
    // Write f-pair-major half2: 32 fp x 32 i = 1024 half2 per array, 4 passes.
#pragma unroll
    for (int p = 0; p < 4; p++) {
        int l = p * 256 + tid;
        int fp = l >> 5;         // 0..31
        int i = l & 31;
        dstC[fp * N + i0 + i] = __floats2half2_rn(sc[2 * fp][i], sc[2 * fp + 1][i]);
        dstS[fp * N + i0 + i] = __floats2half2_rn(ss[2 * fp][i], ss[2 * fp + 1][i]);
    }
    if (blk < 8) out[blk * 256 + tid] = b[0];
}

union U16 { uint4 u; __half2 h[4]; };

__global__ __launch_bounds__(256, 4) void main_kernel(const float* __restrict__ W,
                                                      float* __restrict__ out) {
    // Single chunk covers all 32 f-pairs: 32 x 64 half2 = 8KB per array.
    __shared__ __align__(16) __half2 sCX[FP][BI];
    __shared__ __align__(16) __half2 sSX[FP][BI];
    __shared__ __align__(16) __half2 sCS[FP][BJ];
    __shared__ __align__(16) __half2 sSS[FP][BJ];
    __shared__ float sW[BJ];

    const int tid = threadIdx.x;
    const int tx = tid & 15;   // j-direction (16 threads * TJ=4 -> 64 j)
    const int ty = tid >> 4;   // i-direction (16 threads * TI=4 -> 64 i)
    const int i0 = blockIdx.x * BI;
    const int j0 = blockIdx.y * BJ;

    if (tid < BJ) sW[tid] = W[j0 + tid];

    // Fill: per array 2048 half2 = 512 uint4, 2 rounds of 256.
#pragma unroll
    for (int r = 0; r < 2; r++) {
        int l = r * 256 + tid;
        int fp = l >> 4;            // 0..31
        int q = (l & 15) * 4;       // half2 column, 16B aligned
        *(uint4*)&sCX[fp][q] = *(const uint4*)&g_cX2[fp * BB + i0 + q];
        *(uint4*)&sSX[fp][q] = *(const uint4*)&g_sX2[fp * BB + i0 + q];
        *(uint4*)&sCS[fp][q] = *(const uint4*)&g_cS2[fp * SS + j0 + q];
        *(uint4*)&sSS[fp][q] = *(const uint4*)&g_sS2[fp * SS + j0 + q];
    }
    __syncthreads();

    // acc[a][b] = {prod over even f of t_f, prod over odd f of t_f}
    __half2 acc[TI][TJ];
    const __half2 one2 = __floats2half2_rn(1.0f, 1.0f);
#pragma unroll
    for (int a = 0; a < TI; a++)
#pragma unroll
        for (int b = 0; b < TJ; b++) acc[a][b] = one2;

#pragma unroll 4
    for (int fp = 0; fp < FP; fp++) {
        U16 cx, sx, cj, sj;
        cx.u = *(const uint4*)&sCX[fp][ty * TI];   // 4 i's, each half2 = {f even, f odd}
        sx.u = *(const uint4*)&sSX[fp][ty * TI];
        cj.u = *(const uint4*)&sCS[fp][tx * TJ];   // 4 j's
        sj.u = *(const uint4*)&sSS[fp][tx * TJ];
#pragma unroll
        for (int a = 0; a < TI; a++) {
#pragma unroll
            for (int b = 0; b < TJ; b++) {
                // t2 = {cos((x-s)/2) at f_even, at f_odd}
                __half2 t2 = __hfma2(cx.h[a], cj.h[b], __hmul2(sx.h[a], sj.h[b]));
                acc[a][b] = __hmul2(acc[a][b], t2);
            }
        }
    }

    // K = (P_even * P_odd)^2 in fp32; weight by W; reduce over the 16 tx threads.
#pragma unroll
    for (int a = 0; a < TI; a++) {
        float p = 0.0f;
#pragma unroll
        for (int b = 0; b < TJ; b++) {
            float2 pe = __half22float2(acc[a][b]);
            float pt = pe.x * pe.y;
            p = fmaf(pt * pt, sW[tx * TJ + b], p);
        }
#pragma unroll
        for (int off = 8; off > 0; off >>= 1)
            p += __shfl_down_sync(0xffffffffu, p, off, 16);
        if (tx == 0) atomicAdd(&out[i0 + ty * TI + a], p);
    }
}

extern "C" void kernel_launch(void* const* d_in, const int* in_sizes, int n_in,
                              void* d_out, int out_size) {
    const float* X  = (const float*)d_in[0];  // [2048, 64]
    const float* Sp = (const float*)d_in[1];  // [1024, 64]
    const float* W  = (const float*)d_in[2];  // [1, 1024]
    const float* b  = (const float*)d_in[3];  // [1]
    float* out = (float*)d_out;               // [2048]

    precomp_kernel<<<96, 256>>>(X, Sp, b, out);   // fp16 tables + out=b init

    dim3 grid(BB / BI, SS / BJ);  // 32 x 16 = 512 CTAs
    main_kernel<<<grid, 256>>>(W, out);
}